// round 8
// baseline (speedup 1.0000x reference)
#include <cuda_runtime.h>

// Problem: B=4, D=64, K=32, N=8192. Total floats = 2,097,152 = 524288 float4.
#define Kk 32
#define Dk 64
#define TPB 256
#define GRIDA 2048           // kernel A: 1 float4/thread; blk = bd*8 + chunk
#define GRIDC 1024           // kernel C: 2 float4/thread; blk = bd*4 + chunk

typedef unsigned long long u64;

__device__ float g_partial[GRIDA];   // per-block sum of E (deterministic)
__device__ float g_gamma1[256];      // 1 + gamma(b,d)

__device__ __forceinline__ float ex2(float x) {
    float y; asm("ex2.approx.f32 %0, %1;" : "=f"(y) : "f"(x)); return y;
}
__device__ __forceinline__ u64 pk(float lo, float hi) {
    u64 r; asm("mov.b64 %0, {%1,%2};" : "=l"(r) : "f"(lo), "f"(hi)); return r;
}
__device__ __forceinline__ u64 pku(unsigned lo, unsigned hi) {
    u64 r; asm("mov.b64 %0, {%1,%2};" : "=l"(r) : "r"(lo), "r"(hi)); return r;
}
__device__ __forceinline__ void upk(float& lo, float& hi, u64 v) {
    asm("mov.b64 {%0,%1}, %2;" : "=f"(lo), "=f"(hi) : "l"(v));
}
__device__ __forceinline__ u64 add2(u64 a, u64 b) {
    u64 r; asm("add.rn.f32x2 %0, %1, %2;" : "=l"(r) : "l"(a), "l"(b)); return r;
}
__device__ __forceinline__ u64 mul2(u64 a, u64 b) {
    u64 r; asm("mul.rn.f32x2 %0, %1, %2;" : "=l"(r) : "l"(a), "l"(b)); return r;
}
__device__ __forceinline__ u64 fma2(u64 a, u64 b, u64 c) {
    u64 r; asm("fma.rn.f32x2 %0, %1, %2, %3;" : "=l"(r) : "l"(a), "l"(b), "l"(c)); return r;
}

// ---- Kernel A: E (unscaled) + per-block partial sums ----
__global__ void __launch_bounds__(TPB)
k_encode(const float* __restrict__ X, const float* __restrict__ cw,
         const float* __restrict__ sc, float* __restrict__ out)
{
    //   arg = slx*x^2 + p1*x + p0;  slx = scale*log2e, p1 = -2c*slx, p0 = c^2*slx
    __shared__ uint4 s_cA[Kk];   // (p1,p1,p0,p0) bit-pattern
    __shared__ uint4 s_cB[Kk];   // (sl,sl,nc,nc)
    __shared__ float s_red[TPB / 32];

    const int t   = threadIdx.x;
    const int blk = blockIdx.x;
    const int d   = (blk >> 3) & 63;

    if (t < Kk) {
        const float c   = cw[t * Dk + d];
        const float slx = sc[t * Dk + d] * 1.4426950408889634f;
        const unsigned p1 = __float_as_uint(-2.0f * c * slx);
        const unsigned p0 = __float_as_uint(c * c * slx);
        const unsigned sl = __float_as_uint(slx);
        const unsigned nc = __float_as_uint(-c);
        s_cA[t] = make_uint4(p1, p1, p0, p0);
        s_cB[t] = make_uint4(sl, sl, nc, nc);
    }
    __syncthreads();

    const float4 v = ((const float4*)X)[blk * TPB + t];
    const u64 xa = pk(v.x, v.y), xb = pk(v.z, v.w);
    const u64 xxa = mul2(xa, xa), xxb = mul2(xb, xb);
    u64 dena = 0ull, denb = 0ull, wa = 0ull, wb = 0ull;

    #pragma unroll 8
    for (int k = 0; k < Kk; k++) {
        const uint4 cA = s_cA[k];            // one LDS.128
        const uint4 cB = s_cB[k];            // one LDS.128
        const u64 p1 = pku(cA.x, cA.y), p0 = pku(cA.z, cA.w);
        const u64 sl = pku(cB.x, cB.y), nc = pku(cB.z, cB.w);
        u64 a0 = fma2(sl, xxa, fma2(p1, xa, p0));   // arg <= 0
        u64 a1 = fma2(sl, xxb, fma2(p1, xb, p0));
        float l0, h0, l1, h1;
        upk(l0, h0, a0);
        upk(l1, h1, a1);
        const u64 e0 = pk(ex2(l0), ex2(h0));
        const u64 e1 = pk(ex2(l1), ex2(h1));
        dena = add2(dena, e0);  wa = fma2(e0, nc, wa);   // w = sum e*(-c)
        denb = add2(denb, e1);  wb = fma2(e1, nc, wb);
    }

    const u64 na = fma2(xa, dena, wa);   // num = x*den - sum(e*c)
    const u64 nb = fma2(xb, denb, wb);
    float n0, n1, n2, n3, d0, d1, d2, d3;
    upk(n0, n1, na); upk(n2, n3, nb);
    upk(d0, d1, dena); upk(d2, d3, denb);
    float4 o;
    o.x = __fdividef(n0, d0);
    o.y = __fdividef(n1, d1);
    o.z = __fdividef(n2, d2);
    o.w = __fdividef(n3, d3);
    ((float4*)out)[blk * TPB + t] = o;   // unscaled E; kernel C rescales

    float ssum = (o.x + o.y) + (o.z + o.w);
    #pragma unroll
    for (int off = 16; off > 0; off >>= 1)
        ssum += __shfl_xor_sync(0xffffffffu, ssum, off);
    if ((t & 31) == 0) s_red[t >> 5] = ssum;
    __syncthreads();
    if (t == 0) {
        float s = 0.f;
        #pragma unroll
        for (int w = 0; w < TPB / 32; w++) s += s_red[w];
        g_partial[blk] = s;
    }
}

// ---- Kernel B: one block computes all 256 gamma values ----
__global__ void __launch_bounds__(256)
k_gamma(const float* __restrict__ fw, const float* __restrict__ fb)
{
    __shared__ float s_eg[256];          // E_glob[b][d] / K
    const int t = threadIdx.x;           // t = b*64 + j
    {
        const float* gp = &g_partial[t * 8];
        float s = 0.f;
        #pragma unroll
        for (int r = 0; r < 8; r++) s += __ldcg(gp + r);
        s_eg[t] = s * (1.0f / Kk);
    }
    __syncthreads();
    const int b = t >> 6, i = t & 63;
    float acc = __ldg(fb + i);
    const float* fwr = fw + i * Dk;
    const float* eg  = s_eg + b * Dk;
    #pragma unroll 16
    for (int j = 0; j < Dk; j++) acc = fmaf(eg[j], __ldg(fwr + j), acc);
    g_gamma1[t] = 1.f + 1.f / (1.f + __expf(-acc));   // 1 + sigmoid
}

// ---- Kernel C: pure streaming scale + relu ----
__global__ void __launch_bounds__(TPB)
k_scale(float* __restrict__ out)
{
    const int t   = threadIdx.x;
    const int blk = blockIdx.x;
    const float g = __ldg(&g_gamma1[blk >> 2]);   // uniform per block
    float4* base = (float4*)out + blk * 512;

    #pragma unroll
    for (int i = 0; i < 2; i++) {
        float4* p = base + i * TPB + t;
        float4 o;
        o.x = __ldcg(&p->x); o.y = __ldcg(&p->y);
        o.z = __ldcg(&p->z); o.w = __ldcg(&p->w);
        o.x = fmaxf(o.x * g, 0.f); o.y = fmaxf(o.y * g, 0.f);
        o.z = fmaxf(o.z * g, 0.f); o.w = fmaxf(o.w * g, 0.f);
        *p = o;
    }
}

extern "C" void kernel_launch(void* const* d_in, const int* in_sizes, int n_in,
                              void* d_out, int out_size)
{
    const float* X   = (const float*)d_in[0];  // (B,D,T,H,W)
    const float* cw  = (const float*)d_in[1];  // (K,D)
    const float* sc  = (const float*)d_in[2];  // (K,D)
    const float* fcw = (const float*)d_in[3];  // (D,D)
    const float* fcb = (const float*)d_in[4];  // (D,)
    float* out = (float*)d_out;

    k_encode<<<GRIDA, TPB>>>(X, cw, sc, out);
    k_gamma<<<1, 256>>>(fcw, fcb);
    k_scale<<<GRIDC, TPB>>>(out);
}

// round 9
// speedup vs baseline: 1.0138x; 1.0138x over previous
#include <cuda_runtime.h>

// Problem: B=4, D=64, K=32, N=8192. Total floats = 2,097,152 = 524288 float4.
#define Kk 32
#define Dk 64
#define TPB 256
#define GRIDA 2048           // kernel A: 1 float4/thread; blk = bd*8 + chunk
#define GRIDC 1024           // kernel C: 2 float4/thread

typedef unsigned long long u64;

__device__ unsigned g_count = 0;     // self-resetting "last block" ticket
__device__ float g_partial[GRIDA];   // per-block sum of E (deterministic)
__device__ float g_gamma1[256];      // 1 + gamma(b,d)

__device__ __forceinline__ float ex2(float x) {
    float y; asm("ex2.approx.f32 %0, %1;" : "=f"(y) : "f"(x)); return y;
}
__device__ __forceinline__ u64 pk(float lo, float hi) {
    u64 r; asm("mov.b64 %0, {%1,%2};" : "=l"(r) : "f"(lo), "f"(hi)); return r;
}
__device__ __forceinline__ u64 pku(unsigned lo, unsigned hi) {
    u64 r; asm("mov.b64 %0, {%1,%2};" : "=l"(r) : "r"(lo), "r"(hi)); return r;
}
__device__ __forceinline__ void upk(float& lo, float& hi, u64 v) {
    asm("mov.b64 {%0,%1}, %2;" : "=f"(lo), "=f"(hi) : "l"(v));
}
__device__ __forceinline__ u64 mul2(u64 a, u64 b) {
    u64 r; asm("mul.rn.f32x2 %0, %1, %2;" : "=l"(r) : "l"(a), "l"(b)); return r;
}
__device__ __forceinline__ u64 fma2(u64 a, u64 b, u64 c) {
    u64 r; asm("fma.rn.f32x2 %0, %1, %2, %3;" : "=l"(r) : "l"(a), "l"(b), "l"(c)); return r;
}

// ---- Kernel A: E (unscaled) + partials; LAST block computes gamma ----
__global__ void __launch_bounds__(TPB)
k_encode(const float* __restrict__ X, const float* __restrict__ cw,
         const float* __restrict__ sc, const float* __restrict__ fw,
         const float* __restrict__ fb, float* __restrict__ out)
{
    //   arg = slx*x^2 + p1*x + p0;  slx = scale*log2e, p1 = -2c*slx, p0 = c^2*slx
    __shared__ uint4 s_cA[Kk];        // (p1,p1,p0,p0) bit-pattern (packed pairs)
    __shared__ uint4 s_cB[Kk];        // (sl,sl,nc,--)  nc used as scalar
    __shared__ float s_red[TPB / 32];
    __shared__ float s_eg[256];       // last-block gamma scratch
    __shared__ unsigned s_ticket;

    const int t   = threadIdx.x;
    const int blk = blockIdx.x;
    const int d   = (blk >> 3) & 63;

    if (t < Kk) {
        const float c   = cw[t * Dk + d];
        const float slx = sc[t * Dk + d] * 1.4426950408889634f;
        const unsigned p1 = __float_as_uint(-2.0f * c * slx);
        const unsigned p0 = __float_as_uint(c * c * slx);
        const unsigned sl = __float_as_uint(slx);
        const unsigned nc = __float_as_uint(-c);
        s_cA[t] = make_uint4(p1, p1, p0, p0);
        s_cB[t] = make_uint4(sl, sl, nc, nc);
    }
    __syncthreads();

    const float4 v = ((const float4*)X)[blk * TPB + t];
    const u64 xa = pk(v.x, v.y), xb = pk(v.z, v.w);
    const u64 xxa = mul2(xa, xa), xxb = mul2(xb, xb);
    // scalar accumulators: EX2 outputs consumed directly, no packing movs
    float den0 = 0.f, den1 = 0.f, den2 = 0.f, den3 = 0.f;
    float w0 = 0.f, w1 = 0.f, w2 = 0.f, w3 = 0.f;

    #pragma unroll 8
    for (int k = 0; k < Kk; k++) {
        const uint4 cA = s_cA[k];            // LDS.128 (broadcast)
        const uint4 cB = s_cB[k];            // LDS.128 (broadcast)
        const u64 p1 = pku(cA.x, cA.y), p0 = pku(cA.z, cA.w);
        const u64 sl = pku(cB.x, cB.y);
        const float nc = __uint_as_float(cB.z);
        const u64 a0 = fma2(sl, xxa, fma2(p1, xa, p0));   // arg <= 0
        const u64 a1 = fma2(sl, xxb, fma2(p1, xb, p0));
        float l0, h0, l1, h1;
        upk(l0, h0, a0);                     // free (register aliasing)
        upk(l1, h1, a1);
        const float e0 = ex2(l0), e1 = ex2(h0);
        const float e2 = ex2(l1), e3 = ex2(h1);
        den0 += e0; den1 += e1; den2 += e2; den3 += e3;
        w0 = fmaf(e0, nc, w0); w1 = fmaf(e1, nc, w1);     // w = sum e*(-c)
        w2 = fmaf(e2, nc, w2); w3 = fmaf(e3, nc, w3);
    }

    float4 o;                                 // num = x*den - sum(e*c)
    o.x = __fdividef(fmaf(v.x, den0, w0), den0);
    o.y = __fdividef(fmaf(v.y, den1, w1), den1);
    o.z = __fdividef(fmaf(v.z, den2, w2), den2);
    o.w = __fdividef(fmaf(v.w, den3, w3), den3);
    ((float4*)out)[blk * TPB + t] = o;        // unscaled E; kernel C rescales

    float ssum = (o.x + o.y) + (o.z + o.w);
    #pragma unroll
    for (int off = 16; off > 0; off >>= 1)
        ssum += __shfl_xor_sync(0xffffffffu, ssum, off);
    if ((t & 31) == 0) s_red[t >> 5] = ssum;
    __syncthreads();
    if (t == 0) {
        float s = 0.f;
        #pragma unroll
        for (int w = 0; w < TPB / 32; w++) s += s_red[w];
        g_partial[blk] = s;
        __threadfence();                       // publish partial before ticket
        s_ticket = atomicAdd(&g_count, 1u);
    }
    __syncthreads();

    // ---- Last-finishing block computes the full 256-entry gamma table ----
    if (s_ticket == GRIDA - 1) {
        if (t == 0) g_count = 0;               // reset for next graph replay
        __threadfence();                       // all partials visible (ticket order)
        {                                      // t = b*64 + j
            const float* gp = &g_partial[t * 8];
            float s = 0.f;
            #pragma unroll
            for (int r = 0; r < 8; r++) s += __ldcg(gp + r);
            s_eg[t] = s * (1.0f / Kk);
        }
        __syncthreads();
        const int b = t >> 6, i = t & 63;
        float acc = __ldg(fb + i);
        const float* fwr = fw + i * Dk;
        const float* eg  = s_eg + b * Dk;
        #pragma unroll 16
        for (int j = 0; j < Dk; j++) acc = fmaf(eg[j], __ldg(fwr + j), acc);
        g_gamma1[t] = 1.f + 1.f / (1.f + __expf(-acc));   // 1 + sigmoid
    }
}

// ---- Kernel C: pure streaming scale + relu ----
__global__ void __launch_bounds__(TPB)
k_scale(float* __restrict__ out)
{
    const int t   = threadIdx.x;
    const int blk = blockIdx.x;
    const float g = __ldg(&g_gamma1[blk >> 2]);   // uniform per block
    float4* base = (float4*)out + blk * 512;

    #pragma unroll
    for (int i = 0; i < 2; i++) {
        float4* p = base + i * TPB + t;
        float4 o;
        o.x = __ldcg(&p->x); o.y = __ldcg(&p->y);
        o.z = __ldcg(&p->z); o.w = __ldcg(&p->w);
        o.x = fmaxf(o.x * g, 0.f); o.y = fmaxf(o.y * g, 0.f);
        o.z = fmaxf(o.z * g, 0.f); o.w = fmaxf(o.w * g, 0.f);
        *p = o;
    }
}

extern "C" void kernel_launch(void* const* d_in, const int* in_sizes, int n_in,
                              void* d_out, int out_size)
{
    const float* X   = (const float*)d_in[0];  // (B,D,T,H,W)
    const float* cw  = (const float*)d_in[1];  // (K,D)
    const float* sc  = (const float*)d_in[2];  // (K,D)
    const float* fcw = (const float*)d_in[3];  // (D,D)
    const float* fcb = (const float*)d_in[4];  // (D,)
    float* out = (float*)d_out;

    k_encode<<<GRIDA, TPB>>>(X, cw, sc, fcw, fcb, out);
    k_scale<<<GRIDC, TPB>>>(out);
}

// round 10
// speedup vs baseline: 1.6306x; 1.6083x over previous
#include <cuda_runtime.h>
#include <cuda_fp16.h>

// Problem: B=4, D=64, K=32, N=8192. Total floats = 2,097,152 = 524288 float4.
#define Kk 32
#define Dk 64
#define TPB 256
#define GRIDA 2048           // encode: 1 float4/thread; blk = bd*8 + chunk
#define GRIDC 1024           // scale:  2 float4/thread; blk = bd*4 + chunk

typedef unsigned long long u64;
typedef unsigned int u32;

__device__ float g_partial[GRIDA];   // per-block sum of E (deterministic)

// ---- fp32 packed helpers ----
__device__ __forceinline__ u64 pk(float lo, float hi) {
    u64 r; asm("mov.b64 %0, {%1,%2};" : "=l"(r) : "f"(lo), "f"(hi)); return r;
}
__device__ __forceinline__ u64 pku(u32 lo, u32 hi) {
    u64 r; asm("mov.b64 %0, {%1,%2};" : "=l"(r) : "r"(lo), "r"(hi)); return r;
}
__device__ __forceinline__ void upk(float& lo, float& hi, u64 v) {
    asm("mov.b64 {%0,%1}, %2;" : "=f"(lo), "=f"(hi) : "l"(v));
}
__device__ __forceinline__ u64 mul2(u64 a, u64 b) {
    u64 r; asm("mul.rn.f32x2 %0, %1, %2;" : "=l"(r) : "l"(a), "l"(b)); return r;
}
__device__ __forceinline__ u64 fma2(u64 a, u64 b, u64 c) {
    u64 r; asm("fma.rn.f32x2 %0, %1, %2, %3;" : "=l"(r) : "l"(a), "l"(b), "l"(c)); return r;
}

// ---- fp16x2 helpers (carried in u32) ----
__device__ __forceinline__ u32 cvt2h(float hi, float lo) {   // {lo, hi}
    u32 r; asm("cvt.rn.f16x2.f32 %0, %1, %2;" : "=r"(r) : "f"(hi), "f"(lo)); return r;
}
__device__ __forceinline__ u32 hex2(u32 a) {                 // 2 exps, 1 MUFU op
    u32 r; asm("ex2.approx.f16x2 %0, %1;" : "=r"(r) : "r"(a)); return r;
}
__device__ __forceinline__ u32 hadd2(u32 a, u32 b) {
    u32 r; asm("add.rn.f16x2 %0, %1, %2;" : "=r"(r) : "r"(a), "r"(b)); return r;
}
__device__ __forceinline__ u32 hfma2(u32 a, u32 b, u32 c) {
    u32 r; asm("fma.rn.f16x2 %0, %1, %2, %3;" : "=r"(r) : "r"(a), "r"(b), "r"(c)); return r;
}
__device__ __forceinline__ float lo2f(u32 h) {
    float f; asm("{.reg .f16 l,h; mov.b32 {l,h}, %1; cvt.f32.f16 %0, l;}" : "=f"(f) : "r"(h)); return f;
}
__device__ __forceinline__ float hi2f(u32 h) {
    float f; asm("{.reg .f16 l,h; mov.b32 {l,h}, %1; cvt.f32.f16 %0, h;}" : "=f"(f) : "r"(h)); return f;
}

// ---- Kernel A: E (unscaled) + per-block partial sums ----
// E[n] = x + (sum_k e_k * (-c_k)) / (sum_k e_k),  e_k = exp2(slx*x^2 + p1*x + p0)
__global__ void __launch_bounds__(TPB)
k_encode(const float* __restrict__ X, const float* __restrict__ cw,
         const float* __restrict__ sc, float* __restrict__ out)
{
    __shared__ uint4 s_cA[Kk];   // (p1,p1,p0,p0) fp32 bits
    __shared__ uint4 s_cB[Kk];   // (sl,sl,hc,hc) fp32,fp32,half2,half2
    __shared__ float s_red[TPB / 32];

    const int t   = threadIdx.x;
    const int blk = blockIdx.x;
    const int d   = (blk >> 3) & 63;

    if (t < Kk) {
        const float c   = cw[t * Dk + d];
        const float slx = sc[t * Dk + d] * 1.4426950408889634f;  // fold log2(e)
        const u32 p1 = __float_as_uint(-2.0f * c * slx);
        const u32 p0 = __float_as_uint(c * c * slx);
        const u32 sl = __float_as_uint(slx);
        const u32 hc = cvt2h(-c, -c);                            // half2(-c,-c)
        s_cA[t] = make_uint4(p1, p1, p0, p0);
        s_cB[t] = make_uint4(sl, sl, hc, hc);
    }
    __syncthreads();

    const float4 v = ((const float4*)X)[blk * TPB + t];
    const u64 xa = pk(v.x, v.y), xb = pk(v.z, v.w);
    const u64 xxa = mul2(xa, xa), xxb = mul2(xb, xb);
    u32 da = 0u, db = 0u, wa = 0u, wb = 0u;     // half2 accumulators

    #pragma unroll 8
    for (int k = 0; k < Kk; k++) {
        const uint4 cA = s_cA[k];               // LDS.128 broadcast
        const uint4 cB = s_cB[k];               // LDS.128 broadcast
        const u64 p1 = pku(cA.x, cA.y), p0 = pku(cA.z, cA.w);
        const u64 sl = pku(cB.x, cB.y);
        const u32 hc = cB.z;
        const u64 a0 = fma2(sl, xxa, fma2(p1, xa, p0));   // fp32 args (<= 0)
        const u64 a1 = fma2(sl, xxb, fma2(p1, xb, p0));
        float l0, h0, l1, h1;
        upk(l0, h0, a0);                        // free (register aliasing)
        upk(l1, h1, a1);
        const u32 e0 = hex2(cvt2h(h0, l0));     // 2 exps per MUFU op
        const u32 e1 = hex2(cvt2h(h1, l1));
        da = hadd2(da, e0);  wa = hfma2(e0, hc, wa);      // w = sum e*(-c)
        db = hadd2(db, e1);  wb = hfma2(e1, hc, wb);
    }

    float4 o;                                   // E = x + w/den
    o.x = v.x + __fdividef(lo2f(wa), lo2f(da));
    o.y = v.y + __fdividef(hi2f(wa), hi2f(da));
    o.z = v.z + __fdividef(lo2f(wb), lo2f(db));
    o.w = v.w + __fdividef(hi2f(wb), hi2f(db));
    ((float4*)out)[blk * TPB + t] = o;          // unscaled E; k_scale rescales

    float ssum = (o.x + o.y) + (o.z + o.w);
    #pragma unroll
    for (int off = 16; off > 0; off >>= 1)
        ssum += __shfl_xor_sync(0xffffffffu, ssum, off);
    if ((t & 31) == 0) s_red[t >> 5] = ssum;
    __syncthreads();
    if (t == 0) {
        float s = 0.f;
        #pragma unroll
        for (int w = 0; w < TPB / 32; w++) s += s_red[w];
        g_partial[blk] = s;
    }
}

// ---- Kernel B: warp0 computes gamma (overlapped with E loads), scale + relu ----
__global__ void __launch_bounds__(TPB)
k_scale(const float* __restrict__ fw, const float* __restrict__ fb,
        float* __restrict__ out)
{
    __shared__ float s_g;

    const int t   = threadIdx.x;
    const int blk = blockIdx.x;
    const int bd  = blk >> 2;       // 4 blocks per (b,d) plane
    const int d   = bd & 63;
    const int b   = bd >> 6;

    float4* base = (float4*)out + blk * 512;
    float4* p0 = base + t;
    float4* p1 = base + TPB + t;
    const float4 e0 = __ldcg(p0);   // issued before the gamma work
    const float4 e1 = __ldcg(p1);

    if (t < 32) {
        // gamma(b,d) = sigmoid( sum_j Eglob[b,j]*fw[d,j] + fb[d] )
        float acc = 0.f;
        #pragma unroll
        for (int h = 0; h < 2; h++) {
            const int j = t + h * 32;
            const float* gp = &g_partial[(b * Dk + j) * 8];
            float s = 0.f;
            #pragma unroll
            for (int r = 0; r < 8; r++) s += __ldcg(gp + r);
            acc = fmaf(s * (1.0f / Kk), __ldg(fw + d * Dk + j), acc);
        }
        #pragma unroll
        for (int off = 16; off > 0; off >>= 1)
            acc += __shfl_xor_sync(0xffffffffu, acc, off);
        if (t == 0)
            s_g = 1.f + 1.f / (1.f + __expf(-(acc + __ldg(fb + d))));  // 1+sigmoid
    }
    __syncthreads();

    const float g = s_g;
    float4 o;
    o.x = fmaxf(e0.x * g, 0.f); o.y = fmaxf(e0.y * g, 0.f);
    o.z = fmaxf(e0.z * g, 0.f); o.w = fmaxf(e0.w * g, 0.f);
    *p0 = o;
    o.x = fmaxf(e1.x * g, 0.f); o.y = fmaxf(e1.y * g, 0.f);
    o.z = fmaxf(e1.z * g, 0.f); o.w = fmaxf(e1.w * g, 0.f);
    *p1 = o;
}

extern "C" void kernel_launch(void* const* d_in, const int* in_sizes, int n_in,
                              void* d_out, int out_size)
{
    const float* X   = (const float*)d_in[0];  // (B,D,T,H,W)
    const float* cw  = (const float*)d_in[1];  // (K,D)
    const float* sc  = (const float*)d_in[2];  // (K,D)
    const float* fcw = (const float*)d_in[3];  // (D,D)
    const float* fcb = (const float*)d_in[4];  // (D,)
    float* out = (float*)d_out;

    k_encode<<<GRIDA, TPB>>>(X, cw, sc, out);
    k_scale<<<GRIDC, TPB>>>(fcw, fcb, out);
}